// round 4
// baseline (speedup 1.0000x reference)
#include <cuda_runtime.h>

#define BATCH 8
#define CCH 64
#define HIMG 256
#define WIMG 256
#define NPIX 65536
#define INV_N (1.0f/65536.0f)

// accumulators + rope table (reset/refilled every launch by k0 -> deterministic)
__device__ float  g_ksum[BATCH*CCH];            // 512
__device__ float  g_kv[BATCH*4*16*16];          // 8192: [b][h][d][e]
__device__ float2 g_cs[256*32];                 // [w][j] cos/sin (angle indexed by w axis!)

// ---------------------------------------------------------------------------
__global__ void k0_init() {
    int t = blockIdx.x * 256 + threadIdx.x;     // 0..8191
    if (t < BATCH*CCH) g_ksum[t] = 0.f;
    g_kv[t] = 0.f;
    int wcoord = t >> 5, j = t & 31;
    // theta_j = 10000^(-j/32) = 2^(-j*log2(10000)/32)
    float theta = exp2f(-(float)j * (13.287712379549449f / 32.0f));
    float a = (float)wcoord * theta;
    g_cs[t] = make_float2(cosf(a), sinf(a));
}

// ---------------------------------------------------------------------------
// Pass 1: qk conv at K half-pixels only; accumulate ksum (pre-rope) and
// kv[h][d][e] = sum_n Krope[n,16h+d]*V[n,16h+e]  (unscaled).
// Block: (seg, ch, b). 128 threads = the 128 K pixels of one image row.
__global__ void __launch_bounds__(128) k1_conv_kv(
    const float* __restrict__ x,
    const float* __restrict__ qk_w,
    const float* __restrict__ qk_b)
{
    const int seg = blockIdx.x;          // 0..3 (64 image rows each)
    const int ch  = blockIdx.y;          // 0..127 conv output channel
    const int b   = blockIdx.z;
    const int t   = threadIdx.x;         // 0..127
    const int cx  = ch >> 1;             // input channel
    const float* xb = x + (size_t)b * (CCH*NPIX);
    const float* xc = xb + (size_t)cx * NPIX;

    float w[9];
#pragma unroll
    for (int i = 0; i < 9; i++) w[i] = __ldg(&qk_w[ch*9 + i]);
    const float bias = __ldg(&qk_b[ch]);

    __shared__ float xs[3][264];   // ring of 3 padded rows: xs[slot][1+col]
    __shared__ float vsm[128];     // the two V rows paired with this image row
    __shared__ float red[64*16];   // s=1 partials for kv reduction

    const int s  = t >> 6;               // 0: wi in [64,128), 1: wi in [192,256)
    const int ci = t & 63;                // K column
    const int wi = 64 + s*128 + ci;       // image column (K half-pixels)
    const int h  = ci >> 4;               // head
    const int r0 = seg * 64;

    float acc[16];
#pragma unroll
    for (int e = 0; e < 16; e++) acc[e] = 0.f;
    float ksum = 0.f;

    // preload rows r0-1 and r0 (slot(r) = (r+1)%3)
    for (int rr = 0; rr < 2; rr++) {
        int rrow = r0 - 1 + rr;
        int slot = (rrow + 1) % 3;
        for (int i = t; i < 258; i += 128) {
            int col = i - 1;
            float v = 0.f;
            if (rrow >= 0 && rrow < HIMG && col >= 0 && col < WIMG)
                v = xc[rrow*WIMG + col];
            xs[slot][i] = v;
        }
    }

    for (int hi = r0; hi < r0 + 64; hi++) {
        __syncthreads();                 // prior compute done before overwrite
        {   // load row hi+1
            int rrow = hi + 1;
            int slot = (rrow + 1) % 3;
            for (int i = t; i < 258; i += 128) {
                int col = i - 1;
                float v = 0.f;
                if (rrow < HIMG && col >= 0 && col < WIMG)
                    v = xc[rrow*WIMG + col];
                xs[slot][i] = v;
            }
            // V rows ni_a, ni_b for this image row: contiguous 128 floats
            vsm[t] = xb[(size_t)ch*32768 + (size_t)hi*128 + t];
        }
        __syncthreads();

        const int s0 = hi % 3, s1 = (hi+1) % 3, s2 = (hi+2) % 3;
        float a = bias;
        a += w[0]*xs[s0][wi] + w[1]*xs[s0][wi+1] + w[2]*xs[s0][wi+2];
        a += w[3]*xs[s1][wi] + w[4]*xs[s1][wi+1] + w[5]*xs[s1][wi+2];
        a += w[6]*xs[s2][wi] + w[7]*xs[s2][wi+1] + w[8]*xs[s2][wi+2];
        float kx = (a > 0.f) ? (a + 1.f) : __expf(a);   // elu(a)+1
        ksum += kx;

        // rope: ni = ch*512 + hi*2 + s ; angle indexed by the W coordinate
        // of pixel ni, i.e. (ni & 255). pair = adjacent lanes.
        int ni = ch*512 + hi*2 + s;
        float2 cs = g_cs[(ni & 255)*32 + (ci >> 1)];
        float other = __shfl_xor_sync(0xffffffffu, kx, 1);
        float kr = (ci & 1) ? (other*cs.y + kx*cs.x) : (kx*cs.x - other*cs.y);

        const float* vrow = &vsm[s*64 + h*16];
#pragma unroll
        for (int e = 0; e < 16; e++) acc[e] += kr * vrow[e];
    }

    __syncthreads();
    if (s == 1) {
#pragma unroll
        for (int e = 0; e < 16; e++) red[ci*16 + e] = acc[e];
    }
    __syncthreads();
    if (s == 0) {
        float* dst = &g_kv[b*1024 + h*256 + (ci & 15)*16];
#pragma unroll
        for (int e = 0; e < 16; e++) atomicAdd(&dst[e], acc[e] + red[ci*16 + e]);
    }
    atomicAdd(&g_ksum[b*64 + ci], ksum);
}

// ---------------------------------------------------------------------------
// Pass 2: recompute Q-half conv, elu, z, rope, Qrope@kv*z, + lepe conv,
// transpose-write output. One warp per row ni, 8 rows per block.
__global__ void __launch_bounds__(256) k3_out(
    const float* __restrict__ x,
    const float* __restrict__ qk_w,
    const float* __restrict__ qk_b,
    const float* __restrict__ lepe_w,
    const float* __restrict__ lepe_b,
    float* __restrict__ out)
{
    const int b   = blockIdx.y;
    const int ni0 = blockIdx.x * 8;
    const int wrp = threadIdx.x >> 5;
    const int j   = threadIdx.x & 31;        // column pair index (= rope pair j)
    const int ni  = ni0 + wrp;
    const int ch  = ni >> 9;                  // conv output channel (uniform in block)
    const int cx  = ni >> 10;                 // conv input channel
    const float* xb = x + (size_t)b * (CCH*NPIX);

    __shared__ __align__(16) float kvs[16*64];   // [d][h][e] = d*64+h*16+e
    __shared__ float qx[8][3][68];               // per-warp conv input tile
    __shared__ float qr[8][64];                  // rope'd Q row
    __shared__ float res[8][65];                 // results for transpose write

    for (int i = threadIdx.x; i < 1024; i += 256) {
        int hh = i >> 8, dd = (i >> 4) & 15, ee = i & 15;
        kvs[dd*64 + hh*16 + ee] = g_kv[b*1024 + i];
    }

    // conv input: image row ro = (ni&511)>>1, 64 Q pixels starting at wi0
    const int r   = ni & 511;
    const int ro  = r >> 1;
    const int wi0 = (r & 1) * 128;
    const float* xc = xb + (size_t)cx * NPIX;
#pragma unroll
    for (int dy = 0; dy < 3; dy++) {
        int ry = ro + dy - 1;
        bool rv = (ry >= 0 && ry < HIMG);
        for (int i = j; i < 66; i += 32) {
            int col = wi0 - 1 + i;           // max col = 192 < 256 always
            float v = 0.f;
            if (rv && col >= 0) v = xc[ry*WIMG + col];
            qx[wrp][dy][i] = v;
        }
    }
    __syncthreads();   // covers kvs too

    float w[9];
#pragma unroll
    for (int i = 0; i < 9; i++) w[i] = __ldg(&qk_w[ch*9 + i]);
    float q0 = __ldg(&qk_b[ch]);
    float q1 = q0;
#pragma unroll
    for (int dy = 0; dy < 3; dy++) {
        float v0 = qx[wrp][dy][2*j+0];
        float v1 = qx[wrp][dy][2*j+1];
        float v2 = qx[wrp][dy][2*j+2];
        float v3 = qx[wrp][dy][2*j+3];
        q0 += w[dy*3+0]*v0 + w[dy*3+1]*v1 + w[dy*3+2]*v2;
        q1 += w[dy*3+0]*v1 + w[dy*3+1]*v2 + w[dy*3+2]*v3;
    }
    q0 = (q0 > 0.f) ? (q0 + 1.f) : __expf(q0);
    q1 = (q1 > 0.f) ? (q1 + 1.f) : __expf(q1);

    // z = 1/(q . kmean + eps), per head (8-lane groups)
    const int h = j >> 3;
    float zp = q0 * __ldg(&g_ksum[b*64 + 2*j]) + q1 * __ldg(&g_ksum[b*64 + 2*j + 1]);
    zp += __shfl_xor_sync(0xffffffffu, zp, 1);
    zp += __shfl_xor_sync(0xffffffffu, zp, 2);
    zp += __shfl_xor_sync(0xffffffffu, zp, 4);
    float z = 1.f / (zp * INV_N + 1e-6f);

    // rope Q: angle indexed by the W coordinate of pixel ni = (ni & 255)
    float2 cs = g_cs[(ni & 255)*32 + j];
    qr[wrp][2*j+0] = q0*cs.x - q1*cs.y;
    qr[wrp][2*j+1] = q0*cs.y + q1*cs.x;
    __syncwarp();

    // out = z/n * (Qrope @ kv)
    const int e0 = (2*j) & 15;
    float o0 = 0.f, o1 = 0.f;
#pragma unroll
    for (int d = 0; d < 16; d++) {
        float qv = qr[wrp][h*16 + d];
        float2 kk = *(const float2*)&kvs[d*64 + h*16 + e0];
        o0 += qv * kk.x;
        o1 += qv * kk.y;
    }
    float zz = z * INV_N;
    o0 *= zz; o1 *= zz;

    // lepe: 3x3 depthwise on v-image; v_img[ci, y, xw] = xb[(y*256+xw)*64 + ci]
    const int hi_s = ni >> 8, wi_s = ni & 255;
    float l0 = __ldg(&lepe_b[2*j]);
    float l1 = __ldg(&lepe_b[2*j + 1]);
    float lw0[9], lw1[9];
#pragma unroll
    for (int i = 0; i < 9; i++) {
        lw0[i] = __ldg(&lepe_w[(2*j)*9 + i]);
        lw1[i] = __ldg(&lepe_w[(2*j+1)*9 + i]);
    }
#pragma unroll
    for (int dy = 0; dy < 3; dy++) {
        int ys = hi_s + dy - 1;
        if (ys < 0 || ys >= HIMG) continue;
#pragma unroll
        for (int dx = 0; dx < 3; dx++) {
            int xw = wi_s + dx - 1;
            if (xw < 0 || xw >= WIMG) continue;
            float2 v = *(const float2*)&xb[(size_t)(ys*256 + xw)*64 + 2*j];
            l0 += lw0[dy*3+dx] * v.x;
            l1 += lw1[dy*3+dx] * v.y;
        }
    }

    res[wrp][2*j+0] = o0 + l0;
    res[wrp][2*j+1] = o1 + l1;
    __syncthreads();

    // transpose write: output[b][ci][ni] ; 8 consecutive ni per ci = 32B sector
    float* ob = out + (size_t)b * (CCH*NPIX);
    for (int idx = threadIdx.x; idx < 512; idx += 256) {
        int ci = idx >> 3, kk2 = idx & 7;
        ob[(size_t)ci*NPIX + ni0 + kk2] = res[kk2][ci];
    }
}

// ---------------------------------------------------------------------------
extern "C" void kernel_launch(void* const* d_in, const int* in_sizes, int n_in,
                              void* d_out, int out_size) {
    (void)in_sizes; (void)n_in; (void)out_size;
    const float* x      = (const float*)d_in[0];
    const float* qk_w   = (const float*)d_in[1];
    const float* qk_b   = (const float*)d_in[2];
    const float* lepe_w = (const float*)d_in[3];
    const float* lepe_b = (const float*)d_in[4];
    float* out = (float*)d_out;

    k0_init<<<32, 256>>>();
    k1_conv_kv<<<dim3(4, 128, BATCH), 128>>>(x, qk_w, qk_b);
    k3_out<<<dim3(NPIX/8, BATCH), 256>>>(x, qk_w, qk_b, lepe_w, lepe_b, out);
}

// round 5
// speedup vs baseline: 1.0610x; 1.0610x over previous
#include <cuda_runtime.h>

#define BATCH 8
#define NPIX 65536
#define INV_N (1.0f/65536.0f)
#define FULL 0xffffffffu

// accumulators + rope table (reset/refilled every launch by k0 -> deterministic)
__device__ float  g_ksum[BATCH*64];     // [b][kchan]
__device__ float  g_kv[BATCH*1024];     // [b][h][d][e]
__device__ float2 g_cs[256*32];         // [wcoord][j] cos/sin

// ---------------------------------------------------------------------------
__global__ void k0_init() {
    int t = blockIdx.x * 256 + threadIdx.x;     // 0..8191
    if (t < BATCH*64) g_ksum[t] = 0.f;
    g_kv[t] = 0.f;
    int wc = t >> 5, j = t & 31;
    // theta_j = 10000^(-j/32) = 2^(-j*log2(10000)/32)
    float theta = exp2f(-(float)j * (13.287712379549449f / 32.0f));
    float a = (float)wc * theta;
    g_cs[t] = make_float2(cosf(a), sinf(a));
}

// ---------------------------------------------------------------------------
// Sliding-row conv load: thread owns one column; neighbors via shfl,
// warp-edge lanes patch with direct (L1-hit) loads.
// K kernel version: left halo always in-image; right halo OOB only at wk+1==256.
#define LDROW(rr, L, C, R, WCOL, LEFT_OK) do {                                  \
    int _r = (rr); float _c = 0.f, _l, _rv2;                                    \
    bool _ok = ((unsigned)_r < 256u);                                           \
    if (_ok) _c = __ldg(&xc[_r*256 + (WCOL)]);                                  \
    _l   = __shfl_up_sync(FULL, _c, 1);                                         \
    _rv2 = __shfl_down_sync(FULL, _c, 1);                                       \
    if (lane == 0)  _l   = (_ok && (LEFT_OK)) ? __ldg(&xc[_r*256 + (WCOL) - 1]) : 0.f; \
    if (lane == 31) _rv2 = (_ok && ((WCOL)+1 < 256)) ? __ldg(&xc[_r*256 + (WCOL) + 1]) : 0.f; \
    (L) = _l; (C) = _c; (R) = _rv2; } while(0)

// ---------------------------------------------------------------------------
// Pass 1: conv at K half-pixels (cols 64..127 / 192..255), elu+1, rope,
// accumulate ksum and per-head kv outer products. No barriers in main loop.
// Block: (seg, ch, b), 128 threads.
__global__ void __launch_bounds__(128) k1_kv(
    const float* __restrict__ x,
    const float* __restrict__ qk_w,
    const float* __restrict__ qk_b)
{
    const int seg = blockIdx.x, ch = blockIdx.y, b = blockIdx.z;
    const int t = threadIdx.x, lane = t & 31;
    const int s = t >> 6, cq = t & 63;
    const int wk = 64 + s*128 + cq;           // K image column
    const int h  = cq >> 4;
    const float* xb = x + (size_t)b * (64*NPIX);
    const float* xc = xb + (size_t)(ch >> 1) * NPIX;

    float w[9];
#pragma unroll
    for (int i = 0; i < 9; i++) w[i] = __ldg(&qk_w[ch*9 + i]);
    const float bias = __ldg(&qk_b[ch]);

    float l0,c0,r0, l1,c1,r1, l2,c2,r2;
    const int rs = seg * 64;
    LDROW(rs-1, l0,c0,r0, wk, 1);
    LDROW(rs,   l1,c1,r1, wk, 1);
    LDROW(rs+1, l2,c2,r2, wk, 1);

    float acc[16];
#pragma unroll
    for (int e = 0; e < 16; e++) acc[e] = 0.f;
    float ksum = 0.f;
    const float* vbase = xb + (size_t)ch*32768 + s*64 + h*16;
    const int jj = cq >> 1;
    const bool odd = (cq & 1);

    for (int hi = rs; hi < rs + 64; hi++) {
        float a = bias;
        a += w[0]*l0 + w[1]*c0 + w[2]*r0;
        a += w[3]*l1 + w[4]*c1 + w[5]*r1;
        a += w[6]*l2 + w[7]*c2 + w[8]*r2;
        float kx = (a > 0.f) ? (a + 1.f) : __expf(a);   // elu+1
        ksum += kx;

        // rope: angle indexed by W coordinate of row ni = (2hi+s)&255
        int col = (2*hi + s) & 255;
        float2 cs = g_cs[col*32 + jj];
        float p  = __shfl_xor_sync(FULL, kx, 1);
        float t1 = kx * cs.x, t2 = p * cs.y;
        float kr = odd ? (t1 + t2) : (t1 - t2);

        // V row (broadcast within head, L1)
        const float4* vp = (const float4*)(vbase + (size_t)hi * 128);
        float4 va = vp[0], vb2 = vp[1], vc3 = vp[2], vd = vp[3];
        acc[0] += kr*va.x;  acc[1] += kr*va.y;  acc[2] += kr*va.z;  acc[3] += kr*va.w;
        acc[4] += kr*vb2.x; acc[5] += kr*vb2.y; acc[6] += kr*vb2.z; acc[7] += kr*vb2.w;
        acc[8] += kr*vc3.x; acc[9] += kr*vc3.y; acc[10]+= kr*vc3.z; acc[11]+= kr*vc3.w;
        acc[12]+= kr*vd.x;  acc[13]+= kr*vd.y;  acc[14]+= kr*vd.z;  acc[15]+= kr*vd.w;

        l0=l1; c0=c1; r0=r1;  l1=l2; c1=c2; r1=r2;
        LDROW(hi+2, l2,c2,r2, wk, 1);
    }

    __shared__ float red[64*16];
    if (s == 1) {
#pragma unroll
        for (int e = 0; e < 16; e++) red[cq*16 + e] = acc[e];
    }
    __syncthreads();
    if (s == 0) {
        float* dst = &g_kv[b*1024 + h*256 + (cq & 15)*16];
#pragma unroll
        for (int e = 0; e < 16; e++) atomicAdd(&dst[e], acc[e] + red[cq*16 + e]);
    }
    atomicAdd(&g_ksum[b*64 + cq], ksum);
}

// ---------------------------------------------------------------------------
// Pass 2: conv at Q half-pixels (cols 0..63 / 128..191), elu, z, rope,
// matvec vs register-resident kv, + lepe (coalesced channel loads),
// staged coalesced transpose write. Per-thread constants hoisted.
__global__ void __launch_bounds__(128) k3_out(
    const float* __restrict__ x,
    const float* __restrict__ qk_w,
    const float* __restrict__ qk_b,
    const float* __restrict__ lepe_w,
    const float* __restrict__ lepe_b,
    float* __restrict__ out)
{
    const int seg = blockIdx.x, ch = blockIdx.y, b = blockIdx.z;
    const int t = threadIdx.x, lane = t & 31;
    const int s = t >> 6, cq = t & 63;
    const int wq = s*128 + cq;                 // Q image column
    const int h = cq >> 4, e = cq & 15;
    const float* xb = x + (size_t)b * (64*NPIX);
    const float* xc = xb + (size_t)(ch >> 1) * NPIX;

    // hoisted per-block constants
    float w[9];
#pragma unroll
    for (int i = 0; i < 9; i++) w[i] = __ldg(&qk_w[ch*9 + i]);
    const float bias = __ldg(&qk_b[ch]);
    float lw[9];
#pragma unroll
    for (int i = 0; i < 9; i++) lw[i] = __ldg(&lepe_w[cq*9 + i]);
    const float lb = __ldg(&lepe_b[cq]);
    const float ks = __ldg(&g_ksum[b*64 + cq]);
    float4 kA, kB, kC, kD;
    {
        const float* kvp = &g_kv[b*1024 + h*256 + e];
        kA.x = __ldg(kvp+0*16);  kA.y = __ldg(kvp+1*16);  kA.z = __ldg(kvp+2*16);  kA.w = __ldg(kvp+3*16);
        kB.x = __ldg(kvp+4*16);  kB.y = __ldg(kvp+5*16);  kB.z = __ldg(kvp+6*16);  kB.w = __ldg(kvp+7*16);
        kC.x = __ldg(kvp+8*16);  kC.y = __ldg(kvp+9*16);  kC.z = __ldg(kvp+10*16); kC.w = __ldg(kvp+11*16);
        kD.x = __ldg(kvp+12*16); kD.y = __ldg(kvp+13*16); kD.z = __ldg(kvp+14*16); kD.w = __ldg(kvp+15*16);
    }

    __shared__ __align__(16) float qr[128];
    __shared__ float res[64*65];

    // lepe rows fixed per block: pixel row R = 2ch + (seg>>1)
    const int R = 2*ch + (seg >> 1);
    const float* lr0 = xb + (size_t)(R-1) * 16384;
    const float* lr1 = xb + (size_t)(R)   * 16384;
    const float* lr2 = xb + (size_t)(R+1) * 16384;
    const bool rv0 = (R >= 1), rv2 = (R <= 254);

    float l0,c0,r0, l1,c1,r1, l2,c2,r2;
    const int rs = seg * 64;
    LDROW(rs-1, l0,c0,r0, wq, wq > 0);
    LDROW(rs,   l1,c1,r1, wq, wq > 0);
    LDROW(rs+1, l2,c2,r2, wq, wq > 0);

    const int jj = cq >> 1;
    const bool oddl = (cq & 1);
    const int qbase = t & ~15;

    for (int cb = 0; cb < 2; cb++) {
        const int nbase = ch*512 + seg*128 + cb*64;
        for (int ii = 0; ii < 32; ii++) {
            const int hi = rs + cb*32 + ii;
            // conv + elu
            float a = bias;
            a += w[0]*l0 + w[1]*c0 + w[2]*r0;
            a += w[3]*l1 + w[4]*c1 + w[5]*r1;
            a += w[6]*l2 + w[7]*c2 + w[8]*r2;
            float qv = (a > 0.f) ? (a + 1.f) : __expf(a);

            // z: 16-lane segment reduce of q . ksum
            float zp = qv * ks;
            zp += __shfl_xor_sync(FULL, zp, 1);
            zp += __shfl_xor_sync(FULL, zp, 2);
            zp += __shfl_xor_sync(FULL, zp, 4);
            zp += __shfl_xor_sync(FULL, zp, 8);
            float z = 1.f / (zp * INV_N + 1e-6f);

            // rope (angle = W coord of ni)
            int col = (2*hi + s) & 255;
            float2 cs = g_cs[col*32 + jj];
            float p  = __shfl_xor_sync(FULL, qv, 1);
            float t1 = qv * cs.x, t2 = p * cs.y;
            float qrv = oddl ? (t1 + t2) : (t1 - t2);

            qr[t] = qrv;
            __syncwarp();
            const float4* qp = (const float4*)&qr[qbase];
            float4 qa = qp[0], qb2 = qp[1], qc3 = qp[2], qd = qp[3];
            __syncwarp();

            float o = qa.x*kA.x + qa.y*kA.y + qa.z*kA.z + qa.w*kA.w
                    + qb2.x*kB.x + qb2.y*kB.y + qb2.z*kB.z + qb2.w*kB.w
                    + qc3.x*kC.x + qc3.y*kC.y + qc3.z*kC.z + qc3.w*kC.w
                    + qd.x*kD.x + qd.y*kD.y + qd.z*kD.z + qd.w*kD.w;
            o *= z * INV_N;

            // lepe: pixel (R, col), channel cq; coalesced 128B per warp
            {
                const int off = col*64 + cq;
                const bool cm = (col > 0), cp = (col < 255);
                float la = lb;
                if (rv0) {
                    const float* bp = lr0 + off;
                    la += lw[0] * (cm ? __ldg(bp - 64) : 0.f);
                    la += lw[1] * __ldg(bp);
                    la += lw[2] * (cp ? __ldg(bp + 64) : 0.f);
                }
                {
                    const float* bp = lr1 + off;
                    la += lw[3] * (cm ? __ldg(bp - 64) : 0.f);
                    la += lw[4] * __ldg(bp);
                    la += lw[5] * (cp ? __ldg(bp + 64) : 0.f);
                }
                if (rv2) {
                    const float* bp = lr2 + off;
                    la += lw[6] * (cm ? __ldg(bp - 64) : 0.f);
                    la += lw[7] * __ldg(bp);
                    la += lw[8] * (cp ? __ldg(bp + 64) : 0.f);
                }
                o += la;
            }

            res[cq*65 + 2*ii + s] = o;

            l0=l1; c0=c1; r0=r1;  l1=l2; c1=c2; r1=r2;
            LDROW(hi+2, l2,c2,r2, wq, wq > 0);
        }

        __syncthreads();
        float* ob = out + (size_t)b * (64*NPIX);
        for (int ci = t >> 5; ci < 64; ci += 4) {
            ob[(size_t)ci*NPIX + nbase + lane]      = res[ci*65 + lane];
            ob[(size_t)ci*NPIX + nbase + 32 + lane] = res[ci*65 + 32 + lane];
        }
        __syncthreads();
    }
}

// ---------------------------------------------------------------------------
extern "C" void kernel_launch(void* const* d_in, const int* in_sizes, int n_in,
                              void* d_out, int out_size) {
    (void)in_sizes; (void)n_in; (void)out_size;
    const float* x      = (const float*)d_in[0];
    const float* qk_w   = (const float*)d_in[1];
    const float* qk_b   = (const float*)d_in[2];
    const float* lepe_w = (const float*)d_in[3];
    const float* lepe_b = (const float*)d_in[4];
    float* out = (float*)d_out;

    k0_init<<<32, 256>>>();
    k1_kv<<<dim3(4, 128, BATCH), 128>>>(x, qk_w, qk_b);
    k3_out<<<dim3(4, 128, BATCH), 128>>>(x, qk_w, qk_b, lepe_w, lepe_b, out);
}

// round 6
// speedup vs baseline: 1.0640x; 1.0028x over previous
#include <cuda_runtime.h>

#define BATCH 8
#define NPIX 65536
#define INV_N (1.0f/65536.0f)
#define FULL 0xffffffffu

// accumulators + rope table (reset/refilled every launch by k0 -> deterministic)
__device__ float  g_ksum[BATCH*64];     // [b][kchan]
__device__ float  g_kv[BATCH*1024];     // [b][h][d][e]
__device__ float2 g_cs[256*32];         // [wcoord][j] cos/sin

// ---------------------------------------------------------------------------
__global__ void k0_init() {
    int t = blockIdx.x * 256 + threadIdx.x;     // 0..8191
    if (t < BATCH*64) g_ksum[t] = 0.f;
    g_kv[t] = 0.f;
    int wc = t >> 5, j = t & 31;
    float theta = exp2f(-(float)j * (13.287712379549449f / 32.0f));
    float a = (float)wc * theta;
    g_cs[t] = make_float2(cosf(a), sinf(a));
}

// ---------------------------------------------------------------------------
// Sliding-row conv load: thread owns one column; neighbors via shfl,
// warp-edge lanes patch with direct loads.
#define LDROW(rr, L, C, R, WCOL, LEFT_OK) do {                                  \
    int _r = (rr); float _c = 0.f, _l, _rv2;                                    \
    bool _ok = ((unsigned)_r < 256u);                                           \
    if (_ok) _c = __ldg(&xc[_r*256 + (WCOL)]);                                  \
    _l   = __shfl_up_sync(FULL, _c, 1);                                         \
    _rv2 = __shfl_down_sync(FULL, _c, 1);                                       \
    if (lane == 0)  _l   = (_ok && (LEFT_OK)) ? __ldg(&xc[_r*256 + (WCOL) - 1]) : 0.f; \
    if (lane == 31) _rv2 = (_ok && ((WCOL)+1 < 256)) ? __ldg(&xc[_r*256 + (WCOL) + 1]) : 0.f; \
    (L) = _l; (C) = _c; (R) = _rv2; } while(0)

// ---------------------------------------------------------------------------
// Pass 1: conv at K half-pixels, elu+1, rope, accumulate ksum and per-head kv.
// Software-pipelined: V row and cos/sin prefetched one iteration ahead.
__global__ void __launch_bounds__(128) k1_kv(
    const float* __restrict__ x,
    const float* __restrict__ qk_w,
    const float* __restrict__ qk_b)
{
    const int seg = blockIdx.x, ch = blockIdx.y, b = blockIdx.z;
    const int t = threadIdx.x, lane = t & 31;
    const int s = t >> 6, cq = t & 63;
    const int wk = 64 + s*128 + cq;           // K image column
    const int h  = cq >> 4;
    const float* xb = x + (size_t)b * (64*NPIX);
    const float* xc = xb + (size_t)(ch >> 1) * NPIX;

    float w[9];
#pragma unroll
    for (int i = 0; i < 9; i++) w[i] = __ldg(&qk_w[ch*9 + i]);
    const float bias = __ldg(&qk_b[ch]);

    float l0,c0,r0, l1,c1,r1, l2,c2,r2;
    const int rs = seg * 64;
    LDROW(rs-1, l0,c0,r0, wk, 1);
    LDROW(rs,   l1,c1,r1, wk, 1);
    LDROW(rs+1, l2,c2,r2, wk, 1);

    float acc[16];
#pragma unroll
    for (int e = 0; e < 16; e++) acc[e] = 0.f;
    float ksum = 0.f;
    const float* vbase = xb + (size_t)ch*32768 + s*64 + h*16;
    const int jj = cq >> 1;
    const bool odd = (cq & 1);

    // prefetched state for iteration hi
    float2 cs = __ldg(&g_cs[(((2*rs) + s) & 255)*32 + jj]);
    const float4* vq = (const float4*)(vbase + (size_t)rs * 128);
    float4 va = __ldg(vq+0), vb2 = __ldg(vq+1), vc3 = __ldg(vq+2), vd = __ldg(vq+3);

    for (int hi = rs; hi < rs + 64; hi++) {
        // prefetch next iteration's V row + cos/sin (clamped, value discarded on last)
        int hn = (hi+1 < rs+64) ? hi+1 : rs;
        float2 cs_n = __ldg(&g_cs[(((2*hn) + s) & 255)*32 + jj]);
        const float4* vn = (const float4*)(vbase + (size_t)hn * 128);
        float4 na = __ldg(vn+0), nb = __ldg(vn+1), nc = __ldg(vn+2), nd = __ldg(vn+3);

        float a = bias;
        a += w[0]*l0 + w[1]*c0 + w[2]*r0;
        a += w[3]*l1 + w[4]*c1 + w[5]*r1;
        a += w[6]*l2 + w[7]*c2 + w[8]*r2;
        float kx = (a > 0.f) ? (a + 1.f) : __expf(a);   // elu+1
        ksum += kx;

        float p  = __shfl_xor_sync(FULL, kx, 1);
        float t1 = kx * cs.x, t2 = p * cs.y;
        float kr = odd ? (t1 + t2) : (t1 - t2);

        acc[0] += kr*va.x;  acc[1] += kr*va.y;  acc[2] += kr*va.z;  acc[3] += kr*va.w;
        acc[4] += kr*vb2.x; acc[5] += kr*vb2.y; acc[6] += kr*vb2.z; acc[7] += kr*vb2.w;
        acc[8] += kr*vc3.x; acc[9] += kr*vc3.y; acc[10]+= kr*vc3.z; acc[11]+= kr*vc3.w;
        acc[12]+= kr*vd.x;  acc[13]+= kr*vd.y;  acc[14]+= kr*vd.z;  acc[15]+= kr*vd.w;

        cs = cs_n; va = na; vb2 = nb; vc3 = nc; vd = nd;
        l0=l1; c0=c1; r0=r1;  l1=l2; c1=c2; r1=r2;
        LDROW(hi+2, l2,c2,r2, wk, 1);
    }

    __shared__ float red[64*16];
    if (s == 1) {
#pragma unroll
        for (int e = 0; e < 16; e++) red[cq*16 + e] = acc[e];
    }
    __syncthreads();
    if (s == 0) {
        float* dst = &g_kv[b*1024 + h*256 + (cq & 15)*16];
#pragma unroll
        for (int e = 0; e < 16; e++) atomicAdd(&dst[e], acc[e] + red[cq*16 + e]);
    }
    atomicAdd(&g_ksum[b*64 + cq], ksum);
}

// ---------------------------------------------------------------------------
// Pass 2a: attention only (no lepe). conv at Q half-pixels, elu, z, rope,
// matvec vs register kv, staged coalesced transpose write.
__global__ void __launch_bounds__(128) k3a_attn(
    const float* __restrict__ x,
    const float* __restrict__ qk_w,
    const float* __restrict__ qk_b,
    float* __restrict__ out)
{
    const int seg = blockIdx.x, ch = blockIdx.y, b = blockIdx.z;
    const int t = threadIdx.x, lane = t & 31;
    const int s = t >> 6, cq = t & 63;
    const int wq = s*128 + cq;                 // Q image column
    const int h = cq >> 4, e = cq & 15;
    const float* xb = x + (size_t)b * (64*NPIX);
    const float* xc = xb + (size_t)(ch >> 1) * NPIX;

    float w[9];
#pragma unroll
    for (int i = 0; i < 9; i++) w[i] = __ldg(&qk_w[ch*9 + i]);
    const float bias = __ldg(&qk_b[ch]);
    const float ks = __ldg(&g_ksum[b*64 + cq]);
    float kvv[16];
#pragma unroll
    for (int d = 0; d < 16; d++) kvv[d] = __ldg(&g_kv[b*1024 + h*256 + d*16 + e]);

    __shared__ __align__(16) float qr[2][128];
    __shared__ float res[64*65];

    float l0,c0,r0, l1,c1,r1, l2,c2,r2;
    const int rs = seg * 64;
    LDROW(rs-1, l0,c0,r0, wq, wq > 0);
    LDROW(rs,   l1,c1,r1, wq, wq > 0);
    LDROW(rs+1, l2,c2,r2, wq, wq > 0);

    const int jj = cq >> 1;
    const bool oddl = (cq & 1);
    const int qbase = t & ~15;

    for (int cb = 0; cb < 2; cb++) {
        const int nbase = ch*512 + seg*128 + cb*64;
        float2 cs = __ldg(&g_cs[(((2*(rs + cb*32)) + s) & 255)*32 + jj]);
        for (int ii = 0; ii < 32; ii++) {
            const int hi = rs + cb*32 + ii;
            // prefetch next cos/sin
            int hn = (ii+1 < 32) ? hi+1 : hi;
            float2 cs_n = __ldg(&g_cs[(((2*hn) + s) & 255)*32 + jj]);

            // conv + elu
            float a = bias;
            a += w[0]*l0 + w[1]*c0 + w[2]*r0;
            a += w[3]*l1 + w[4]*c1 + w[5]*r1;
            a += w[6]*l2 + w[7]*c2 + w[8]*r2;
            float qv = (a > 0.f) ? (a + 1.f) : __expf(a);

            // z: 16-lane segment reduce of q . ksum
            float zp = qv * ks;
            zp += __shfl_xor_sync(FULL, zp, 1);
            zp += __shfl_xor_sync(FULL, zp, 2);
            zp += __shfl_xor_sync(FULL, zp, 4);
            zp += __shfl_xor_sync(FULL, zp, 8);
            float z = 1.f / (zp * INV_N + 1e-6f);

            // rope (angle = W coord of ni)
            float p  = __shfl_xor_sync(FULL, qv, 1);
            float t1 = qv * cs.x, t2 = p * cs.y;
            float qrv = oddl ? (t1 + t2) : (t1 - t2);

            // stage qrope (double buffered, one syncwarp)
            const int buf = ii & 1;
            qr[buf][t] = qrv;
            __syncwarp();
            const float4* qp = (const float4*)&qr[buf][qbase];
            float4 qa = qp[0], qb2 = qp[1], qc3 = qp[2], qd = qp[3];

            float o = qa.x*kvv[0] + qa.y*kvv[1] + qa.z*kvv[2] + qa.w*kvv[3]
                    + qb2.x*kvv[4] + qb2.y*kvv[5] + qb2.z*kvv[6] + qb2.w*kvv[7]
                    + qc3.x*kvv[8] + qc3.y*kvv[9] + qc3.z*kvv[10] + qc3.w*kvv[11]
                    + qd.x*kvv[12] + qd.y*kvv[13] + qd.z*kvv[14] + qd.w*kvv[15];
            o *= z * INV_N;

            res[cq*65 + 2*ii + s] = o;

            cs = cs_n;
            l0=l1; c0=c1; r0=r1;  l1=l2; c1=c2; r1=r2;
            LDROW(hi+2, l2,c2,r2, wq, wq > 0);
        }

        __syncthreads();
        float* ob = out + (size_t)b * (64*NPIX);
        for (int ci = t >> 5; ci < 64; ci += 4) {
            ob[(size_t)ci*NPIX + nbase + lane]      = res[ci*65 + lane];
            ob[(size_t)ci*NPIX + nbase + 32 + lane] = res[ci*65 + 32 + lane];
        }
        __syncthreads();
    }
}

// ---------------------------------------------------------------------------
// Pass 2b: lepe depthwise 3x3 on the channel-minor v-image, vectorized float4
// across channels, sliding window across columns, RMW into out.
// Block: (gx 0..3, R 0..255, b). Thread: c4 = 4-channel group, cbk = 8-col strip.
#define LEPE_LD4(dst, ri, col) do {                                             \
    if (rv##ri && (unsigned)(col) < 256u)                                       \
        dst = __ldg((const float4*)(rp##ri + (size_t)(col)*64));                \
    else dst = make_float4(0.f,0.f,0.f,0.f); } while(0)

__global__ void __launch_bounds__(128) k3l_lepe(
    const float* __restrict__ x,
    const float* __restrict__ lepe_w,
    const float* __restrict__ lepe_b,
    float* __restrict__ out)
{
    const int gx = blockIdx.x, R = blockIdx.y, b = blockIdx.z;
    const int t = threadIdx.x;
    const int c4 = t & 15;              // channels [4*c4, 4*c4+4)
    const int cbk = t >> 4;             // 0..7
    const int col0 = gx*64 + cbk*8;
    const float* xb = x + (size_t)b * (64*NPIX);
    float* ob = out + (size_t)b * (64*NPIX);

    float lw[3][3][4], lb[4];
#pragma unroll
    for (int k = 0; k < 4; k++) {
        int chn = c4*4 + k;
        lb[k] = __ldg(&lepe_b[chn]);
#pragma unroll
        for (int ty = 0; ty < 3; ty++)
#pragma unroll
            for (int tx = 0; tx < 3; tx++)
                lw[ty][tx][k] = __ldg(&lepe_w[chn*9 + ty*3 + tx]);
    }

    const bool rv0 = (R >= 1), rv1 = true, rv2 = (R <= 254);
    const float* rp0 = xb + (size_t)(R-1)*16384 + c4*4;
    const float* rp1 = xb + (size_t)(R  )*16384 + c4*4;
    const float* rp2 = xb + (size_t)(R+1)*16384 + c4*4;

    float4 P0, P1, P2, C0, C1, C2;
    LEPE_LD4(P0, 0, col0-1); LEPE_LD4(P1, 1, col0-1); LEPE_LD4(P2, 2, col0-1);
    LEPE_LD4(C0, 0, col0);   LEPE_LD4(C1, 1, col0);   LEPE_LD4(C2, 2, col0);

#pragma unroll
    for (int gg = 0; gg < 2; gg++) {
        float accv[4][4];
#pragma unroll
        for (int i = 0; i < 4; i++) {
            const int col = col0 + gg*4 + i;
            float4 N0, N1, N2;
            LEPE_LD4(N0, 0, col+1); LEPE_LD4(N1, 1, col+1); LEPE_LD4(N2, 2, col+1);

#pragma unroll
            for (int k = 0; k < 4; k++) {
                float p0 = (k==0?P0.x:k==1?P0.y:k==2?P0.z:P0.w);
                float c0v= (k==0?C0.x:k==1?C0.y:k==2?C0.z:C0.w);
                float n0 = (k==0?N0.x:k==1?N0.y:k==2?N0.z:N0.w);
                float p1 = (k==0?P1.x:k==1?P1.y:k==2?P1.z:P1.w);
                float c1v= (k==0?C1.x:k==1?C1.y:k==2?C1.z:C1.w);
                float n1 = (k==0?N1.x:k==1?N1.y:k==2?N1.z:N1.w);
                float p2 = (k==0?P2.x:k==1?P2.y:k==2?P2.z:P2.w);
                float c2v= (k==0?C2.x:k==1?C2.y:k==2?C2.z:C2.w);
                float n2 = (k==0?N2.x:k==1?N2.y:k==2?N2.z:N2.w);
                float v = lb[k];
                v += lw[0][0][k]*p0 + lw[0][1][k]*c0v + lw[0][2][k]*n0;
                v += lw[1][0][k]*p1 + lw[1][1][k]*c1v + lw[1][2][k]*n1;
                v += lw[2][0][k]*p2 + lw[2][1][k]*c2v + lw[2][2][k]*n2;
                accv[k][i] = v;
            }
            P0 = C0; P1 = C1; P2 = C2;
            C0 = N0; C1 = N1; C2 = N2;
        }
        // RMW out: per channel, 4 consecutive cols = float4
#pragma unroll
        for (int k = 0; k < 4; k++) {
            float* base = ob + (size_t)(c4*4 + k)*NPIX + R*256 + col0 + gg*4;
            float4 cur = *(const float4*)base;
            cur.x += accv[k][0]; cur.y += accv[k][1];
            cur.z += accv[k][2]; cur.w += accv[k][3];
            *(float4*)base = cur;
        }
    }
}

// ---------------------------------------------------------------------------
extern "C" void kernel_launch(void* const* d_in, const int* in_sizes, int n_in,
                              void* d_out, int out_size) {
    (void)in_sizes; (void)n_in; (void)out_size;
    const float* x      = (const float*)d_in[0];
    const float* qk_w   = (const float*)d_in[1];
    const float* qk_b   = (const float*)d_in[2];
    const float* lepe_w = (const float*)d_in[3];
    const float* lepe_b = (const float*)d_in[4];
    float* out = (float*)d_out;

    k0_init<<<32, 256>>>();
    k1_kv<<<dim3(4, 128, BATCH), 128>>>(x, qk_w, qk_b);
    k3a_attn<<<dim3(4, 128, BATCH), 128>>>(x, qk_w, qk_b, out);
    k3l_lepe<<<dim3(4, 256, BATCH), 128>>>(x, lepe_w, lepe_b, out);
}

// round 7
// speedup vs baseline: 1.4584x; 1.3707x over previous
#include <cuda_runtime.h>

#define BATCH 8
#define NPIX 65536
#define INV_N (1.0f/65536.0f)
#define FULL 0xffffffffu

// accumulators + rope table (reset/refilled every launch by k0 -> deterministic)
__device__ float  g_ksum[BATCH*64];     // [b][kchan]
__device__ float  g_kv[BATCH*1024];     // [b][h][d][e]
__device__ float2 g_cs[256*32];         // [wcoord][j] cos/sin

// ---------------------------------------------------------------------------
__global__ void k0_init() {
    int t = blockIdx.x * 256 + threadIdx.x;     // 0..8191
    if (t < BATCH*64) g_ksum[t] = 0.f;
    g_kv[t] = 0.f;
    int wc = t >> 5, j = t & 31;
    float theta = exp2f(-(float)j * (13.287712379549449f / 32.0f));
    float a = (float)wc * theta;
    g_cs[t] = make_float2(cosf(a), sinf(a));
}

// ---------------------------------------------------------------------------
// Sliding-row loader, pair version: thread owns 2 adjacent columns (COL, COL+1).
// Loads float2; left/right halo via shfl; edge lanes patch with direct loads.
#define LDROW2(rr, L, C, R, COL, LOK, ROK) do {                                 \
    int _r = (rr); float2 _c = make_float2(0.f, 0.f); float _l, _rv;            \
    bool _ok = ((unsigned)_r < 256u);                                           \
    if (_ok) _c = __ldg((const float2*)&xc[_r*256 + (COL)]);                    \
    _l  = __shfl_up_sync(FULL, _c.y, 1);                                        \
    _rv = __shfl_down_sync(FULL, _c.x, 1);                                      \
    if (lane == 0)  _l  = (_ok && (LOK)) ? __ldg(&xc[_r*256 + (COL) - 1]) : 0.f; \
    if (lane == 31) _rv = (_ok && (ROK)) ? __ldg(&xc[_r*256 + (COL) + 2]) : 0.f; \
    (L) = _l; (C) = _c; (R) = _rv; } while(0)

// ---------------------------------------------------------------------------
// Pass 1: conv at K half-pixels, elu+1, in-thread rope (channel pair), kv+ksum.
// Warp = (s, rowgroup); lane j owns channels (2j, 2j+1) = adjacent columns.
__global__ void __launch_bounds__(128) k1_kv(
    const float* __restrict__ x,
    const float* __restrict__ qk_w,
    const float* __restrict__ qk_b)
{
    const int seg = blockIdx.x, ch = blockIdx.y, b = blockIdx.z;
    const int t = threadIdx.x;
    const int lane = t & 31;            // j: channel pair index
    const int w_id = t >> 5;
    const int s = w_id & 1, rg = w_id >> 1;
    const int j = lane;
    const int wk = 64 + s*128 + 2*j;    // image column of channel 2j (K half)
    const int h = j >> 3;
    const float* xb = x + (size_t)b * (64*NPIX);
    const float* xc = xb + (size_t)(ch >> 1) * NPIX;

    float w[9];
#pragma unroll
    for (int i = 0; i < 9; i++) w[i] = __ldg(&qk_w[ch*9 + i]);
    const float bias = __ldg(&qk_b[ch]);

    const int rs = seg*64 + rg*32;
    float l0,r0,l1,r1,l2,r2; float2 c0,c1,c2;
    const bool rok = (wk + 2 < 256);
    LDROW2(rs-1, l0,c0,r0, wk, 1, rok);
    LDROW2(rs,   l1,c1,r1, wk, 1, rok);
    LDROW2(rs+1, l2,c2,r2, wk, 1, rok);

    float acc0[16], acc1[16];
#pragma unroll
    for (int e = 0; e < 16; e++) { acc0[e] = 0.f; acc1[e] = 0.f; }
    float ksum0 = 0.f, ksum1 = 0.f;
    const float* vbase = xb + (size_t)ch*32768 + s*64 + h*16;

    // prefetched state
    float2 cs = __ldg(&g_cs[(((2*rs) + s) & 255)*32 + j]);
    const float4* vq = (const float4*)(vbase + (size_t)rs * 128);
    float4 va = __ldg(vq+0), vb2 = __ldg(vq+1), vc3 = __ldg(vq+2), vd = __ldg(vq+3);

    for (int hi = rs; hi < rs + 32; hi++) {
        int hn = (hi+1 < rs+32) ? hi+1 : rs;
        float2 cs_n = __ldg(&g_cs[(((2*hn) + s) & 255)*32 + j]);
        const float4* vn = (const float4*)(vbase + (size_t)hn * 128);
        float4 na = __ldg(vn+0), nb = __ldg(vn+1), nc = __ldg(vn+2), nd = __ldg(vn+3);

        float a0 = bias + w[0]*l0   + w[1]*c0.x + w[2]*c0.y
                        + w[3]*l1   + w[4]*c1.x + w[5]*c1.y
                        + w[6]*l2   + w[7]*c2.x + w[8]*c2.y;
        float a1 = bias + w[0]*c0.x + w[1]*c0.y + w[2]*r0
                        + w[3]*c1.x + w[4]*c1.y + w[5]*r1
                        + w[6]*c2.x + w[7]*c2.y + w[8]*r2;
        float k0v = (a0 > 0.f) ? (a0 + 1.f) : __expf(a0);
        float k1v = (a1 > 0.f) ? (a1 + 1.f) : __expf(a1);
        ksum0 += k0v; ksum1 += k1v;

        // in-thread rope
        float kr0 = k0v*cs.x - k1v*cs.y;
        float kr1 = k0v*cs.y + k1v*cs.x;

        acc0[0] += kr0*va.x;  acc0[1] += kr0*va.y;  acc0[2] += kr0*va.z;  acc0[3] += kr0*va.w;
        acc0[4] += kr0*vb2.x; acc0[5] += kr0*vb2.y; acc0[6] += kr0*vb2.z; acc0[7] += kr0*vb2.w;
        acc0[8] += kr0*vc3.x; acc0[9] += kr0*vc3.y; acc0[10]+= kr0*vc3.z; acc0[11]+= kr0*vc3.w;
        acc0[12]+= kr0*vd.x;  acc0[13]+= kr0*vd.y;  acc0[14]+= kr0*vd.z;  acc0[15]+= kr0*vd.w;
        acc1[0] += kr1*va.x;  acc1[1] += kr1*va.y;  acc1[2] += kr1*va.z;  acc1[3] += kr1*va.w;
        acc1[4] += kr1*vb2.x; acc1[5] += kr1*vb2.y; acc1[6] += kr1*vb2.z; acc1[7] += kr1*vb2.w;
        acc1[8] += kr1*vc3.x; acc1[9] += kr1*vc3.y; acc1[10]+= kr1*vc3.z; acc1[11]+= kr1*vc3.w;
        acc1[12]+= kr1*vd.x;  acc1[13]+= kr1*vd.y;  acc1[14]+= kr1*vd.z;  acc1[15]+= kr1*vd.w;

        cs = cs_n; va = na; vb2 = nb; vc3 = nc; vd = nd;
        l0=l1; c0=c1; r0=r1;  l1=l2; c1=c2; r1=r2;
        LDROW2(hi+2, l2,c2,r2, wk, 1, rok);
    }

    // block reduction of 4 warp-copies, then atomics
    __shared__ float red[32*128];       // [idx 0..31][w*32+j]
    __shared__ float red2[256];
#pragma unroll
    for (int e = 0; e < 16; e++) {
        red[e*128      + w_id*32 + j] = acc0[e];
        red[(16+e)*128 + w_id*32 + j] = acc1[e];
    }
    red2[w_id*64 + 2*j]     = ksum0;
    red2[w_id*64 + 2*j + 1] = ksum1;
    __syncthreads();
#pragma unroll
    for (int q = 0; q < 8; q++) {
        int s2 = t*8 + q;
        int idx = s2 >> 5, jv = s2 & 31;
        float v = red[idx*128 + jv] + red[idx*128 + 32 + jv]
                + red[idx*128 + 64 + jv] + red[idx*128 + 96 + jv];
        int d = 2*(jv & 7) + (idx >> 4);
        int e = idx & 15;
        int hh = jv >> 3;
        atomicAdd(&g_kv[b*1024 + hh*256 + d*16 + e], v);
    }
    if (t < 64) {
        float v = red2[t] + red2[64+t] + red2[128+t] + red2[192+t];
        atomicAdd(&g_ksum[b*64 + t], v);
    }
}

// ---------------------------------------------------------------------------
// Pass 2a: attention. Thread owns channel pair; in-thread rope; 8-lane z reduce;
// matvec vs float2 kv registers; staged coalesced transpose write.
__global__ void __launch_bounds__(128) k3a_attn(
    const float* __restrict__ x,
    const float* __restrict__ qk_w,
    const float* __restrict__ qk_b,
    float* __restrict__ out)
{
    const int seg = blockIdx.x, ch = blockIdx.y, b = blockIdx.z;
    const int t = threadIdx.x;
    const int lane = t & 31;            // j
    const int w_id = t >> 5;
    const int s = w_id & 1, rg = w_id >> 1;
    const int j = lane;
    const int wq = s*128 + 2*j;         // image column of channel 2j (Q half)
    const int h = j >> 3, e0 = 2*(j & 7);
    const float* xb = x + (size_t)b * (64*NPIX);
    const float* xc = xb + (size_t)(ch >> 1) * NPIX;

    float w[9];
#pragma unroll
    for (int i = 0; i < 9; i++) w[i] = __ldg(&qk_w[ch*9 + i]);
    const float bias = __ldg(&qk_b[ch]);
    const float ks0 = __ldg(&g_ksum[b*64 + 2*j]);
    const float ks1 = __ldg(&g_ksum[b*64 + 2*j + 1]);
    float2 kv2[16];
#pragma unroll
    for (int d = 0; d < 16; d++)
        kv2[d] = __ldg((const float2*)&g_kv[b*1024 + h*256 + d*16 + e0]);

    __shared__ __align__(16) float qs[4][2][64];
    __shared__ float res[2][64][66];

    const int rs = seg*64 + rg*32;
    const bool lok = (wq > 0);
    float l0,r0,l1,r1,l2,r2; float2 c0,c1,c2;
    LDROW2(rs-1, l0,c0,r0, wq, lok, 1);
    LDROW2(rs,   l1,c1,r1, wq, lok, 1);
    LDROW2(rs+1, l2,c2,r2, wq, lok, 1);

    float2 cs = __ldg(&g_cs[(((2*rs) + s) & 255)*32 + j]);

    for (int ii = 0; ii < 32; ii++) {
        const int hi = rs + ii;
        int hn = (ii+1 < 32) ? hi+1 : hi;
        float2 cs_n = __ldg(&g_cs[(((2*hn) + s) & 255)*32 + j]);

        float a0 = bias + w[0]*l0   + w[1]*c0.x + w[2]*c0.y
                        + w[3]*l1   + w[4]*c1.x + w[5]*c1.y
                        + w[6]*l2   + w[7]*c2.x + w[8]*c2.y;
        float a1 = bias + w[0]*c0.x + w[1]*c0.y + w[2]*r0
                        + w[3]*c1.x + w[4]*c1.y + w[5]*r1
                        + w[6]*c2.x + w[7]*c2.y + w[8]*r2;
        float q0 = (a0 > 0.f) ? (a0 + 1.f) : __expf(a0);
        float q1 = (a1 > 0.f) ? (a1 + 1.f) : __expf(a1);

        // z: 8-lane segment reduce (16 channels per head = 8 lanes)
        float zp = q0*ks0 + q1*ks1;
        zp += __shfl_xor_sync(FULL, zp, 1);
        zp += __shfl_xor_sync(FULL, zp, 2);
        zp += __shfl_xor_sync(FULL, zp, 4);
        float z = 1.f / (zp * INV_N + 1e-6f);

        // in-thread rope
        float qr0 = q0*cs.x - q1*cs.y;
        float qr1 = q0*cs.y + q1*cs.x;

        const int buf = ii & 1;
        *(float2*)&qs[w_id][buf][2*j] = make_float2(qr0, qr1);
        __syncwarp();
        const float4* qp = (const float4*)&qs[w_id][buf][h*16];
        float4 qa = qp[0], qb2 = qp[1], qc3 = qp[2], qd = qp[3];

        float o0 = qa.x*kv2[0].x  + qa.y*kv2[1].x  + qa.z*kv2[2].x  + qa.w*kv2[3].x
                 + qb2.x*kv2[4].x + qb2.y*kv2[5].x + qb2.z*kv2[6].x + qb2.w*kv2[7].x
                 + qc3.x*kv2[8].x + qc3.y*kv2[9].x + qc3.z*kv2[10].x+ qc3.w*kv2[11].x
                 + qd.x*kv2[12].x + qd.y*kv2[13].x + qd.z*kv2[14].x + qd.w*kv2[15].x;
        float o1 = qa.x*kv2[0].y  + qa.y*kv2[1].y  + qa.z*kv2[2].y  + qa.w*kv2[3].y
                 + qb2.x*kv2[4].y + qb2.y*kv2[5].y + qb2.z*kv2[6].y + qb2.w*kv2[7].y
                 + qc3.x*kv2[8].y + qc3.y*kv2[9].y + qc3.z*kv2[10].y+ qc3.w*kv2[11].y
                 + qd.x*kv2[12].y + qd.y*kv2[13].y + qd.z*kv2[14].y + qd.w*kv2[15].y;
        float zz = z * INV_N;
        o0 *= zz; o1 *= zz;

        const int pos = 2*(rg*32 + ii) + s;     // 0..127
        const int chunk = pos >> 6, p = pos & 63;
        res[chunk][2*j][p]   = o0;
        res[chunk][2*j+1][p] = o1;

        cs = cs_n;
        l0=l1; c0=c1; r0=r1;  l1=l2; c1=c2; r1=r2;
        LDROW2(hi+2, l2,c2,r2, wq, lok, 1);
    }

    __syncthreads();
    float* ob = out + (size_t)b * (64*NPIX);
    const int nbase = ch*512 + seg*128;
    for (int ci = w_id; ci < 64; ci += 4) {
        float2 v0 = *(const float2*)&res[0][ci][2*lane];
        float2 v1 = *(const float2*)&res[1][ci][2*lane];
        *(float2*)&ob[(size_t)ci*NPIX + nbase + 2*lane]      = v0;
        *(float2*)&ob[(size_t)ci*NPIX + nbase + 64 + 2*lane] = v1;
    }
}

// ---------------------------------------------------------------------------
// Pass 2b: lepe 3x3 depthwise on channel-minor v-image. Lane = channel pair,
// sliding across columns: warp load = 256B contiguous (2 wavefronts), no shfl.
__global__ void __launch_bounds__(128) k3l_lepe(
    const float* __restrict__ x,
    const float* __restrict__ lepe_w,
    const float* __restrict__ lepe_b,
    float* __restrict__ out)
{
    const int bx = blockIdx.x, R = blockIdx.y, b = blockIdx.z;
    const int t = threadIdx.x, j = t & 31, cg = t >> 5;
    const int col0 = bx*64 + cg*16;
    const float* xb = x + (size_t)b * (64*NPIX);
    float* ob = out + (size_t)b * (64*NPIX);

    float lw0[9], lw1[9];
#pragma unroll
    for (int i = 0; i < 9; i++) {
        lw0[i] = __ldg(&lepe_w[(2*j)*9 + i]);
        lw1[i] = __ldg(&lepe_w[(2*j+1)*9 + i]);
    }
    const float lb0 = __ldg(&lepe_b[2*j]);
    const float lb1 = __ldg(&lepe_b[2*j + 1]);

    const bool rv0 = (R >= 1), rv2 = (R <= 254);
    const float* rp0 = xb + ((size_t)(R-1)*256)*64 + 2*j;
    const float* rp1 = xb + ((size_t)(R  )*256)*64 + 2*j;
    const float* rp2 = xb + ((size_t)(R+1)*256)*64 + 2*j;

    __shared__ float res[64*66];

#define LPLD(rp, rv, col) ((rv && (unsigned)(col) < 256u) ? \
        __ldg((const float2*)((rp) + (size_t)(col)*64)) : make_float2(0.f,0.f))

    float2 P0 = LPLD(rp0, rv0, col0-1), P1 = LPLD(rp1, true, col0-1), P2 = LPLD(rp2, rv2, col0-1);
    float2 C0 = LPLD(rp0, rv0, col0),   C1 = LPLD(rp1, true, col0),   C2 = LPLD(rp2, rv2, col0);

#pragma unroll
    for (int i = 0; i < 16; i++) {
        const int col = col0 + i;
        float2 N0 = LPLD(rp0, rv0, col+1);
        float2 N1 = LPLD(rp1, true, col+1);
        float2 N2 = LPLD(rp2, rv2, col+1);

        float o0 = lb0, o1 = lb1;
        o0 += lw0[0]*P0.x + lw0[1]*C0.x + lw0[2]*N0.x;
        o0 += lw0[3]*P1.x + lw0[4]*C1.x + lw0[5]*N1.x;
        o0 += lw0[6]*P2.x + lw0[7]*C2.x + lw0[8]*N2.x;
        o1 += lw1[0]*P0.y + lw1[1]*C0.y + lw1[2]*N0.y;
        o1 += lw1[3]*P1.y + lw1[4]*C1.y + lw1[5]*N1.y;
        o1 += lw1[6]*P2.y + lw1[7]*C2.y + lw1[8]*N2.y;

        res[(2*j)*66 + cg*16 + i]   = o0;
        res[(2*j+1)*66 + cg*16 + i] = o1;

        P0 = C0; P1 = C1; P2 = C2;
        C0 = N0; C1 = N1; C2 = N2;
    }
    __syncthreads();

    const int rowoff = R*256 + bx*64;
    for (int ci = cg; ci < 64; ci += 4) {
        float* base = ob + (size_t)ci*NPIX + rowoff + 2*j;
        float2 cur = *(const float2*)base;
        float2 add = *(const float2*)&res[ci*66 + 2*j];
        cur.x += add.x; cur.y += add.y;
        *(float2*)base = cur;
    }
#undef LPLD
}

// ---------------------------------------------------------------------------
extern "C" void kernel_launch(void* const* d_in, const int* in_sizes, int n_in,
                              void* d_out, int out_size) {
    (void)in_sizes; (void)n_in; (void)out_size;
    const float* x      = (const float*)d_in[0];
    const float* qk_w   = (const float*)d_in[1];
    const float* qk_b   = (const float*)d_in[2];
    const float* lepe_w = (const float*)d_in[3];
    const float* lepe_b = (const float*)d_in[4];
    float* out = (float*)d_out;

    k0_init<<<32, 256>>>();
    k1_kv<<<dim3(4, 128, BATCH), 128>>>(x, qk_w, qk_b);
    k3a_attn<<<dim3(4, 128, BATCH), 128>>>(x, qk_w, qk_b, out);
    k3l_lepe<<<dim3(4, 256, BATCH), 128>>>(x, lepe_w, lepe_b, out);
}

// round 8
// speedup vs baseline: 1.4603x; 1.0013x over previous
#include <cuda_runtime.h>

#define BATCH 8
#define NPIX 65536
#define INV_N (1.0f/65536.0f)
#define FULL 0xffffffffu

// accumulators + rope table (reset/refilled every launch by k0 -> deterministic)
__device__ float  g_ksum[BATCH*64];     // [b][kchan]
__device__ float  g_kv[BATCH*1024];     // [b][h][d][e]
__device__ float2 g_cs[256*32];         // [wcoord][j] cos/sin

// ---------------------------------------------------------------------------
__global__ void k0_init() {
    int t = blockIdx.x * 256 + threadIdx.x;     // 0..8191
    if (t < BATCH*64) g_ksum[t] = 0.f;
    g_kv[t] = 0.f;
    int wc = t >> 5, j = t & 31;
    float theta = exp2f(-(float)j * (13.287712379549449f / 32.0f));
    float a = (float)wc * theta;
    g_cs[t] = make_float2(cosf(a), sinf(a));
}

// ---------------------------------------------------------------------------
// Sliding-row loader, pair version: thread owns 2 adjacent columns (COL, COL+1).
#define LDROW2(rr, L, C, R, COL, LOK, ROK) do {                                 \
    int _r = (rr); float2 _c = make_float2(0.f, 0.f); float _l, _rv;            \
    bool _ok = ((unsigned)_r < 256u);                                           \
    if (_ok) _c = __ldg((const float2*)&xc[_r*256 + (COL)]);                    \
    _l  = __shfl_up_sync(FULL, _c.y, 1);                                        \
    _rv = __shfl_down_sync(FULL, _c.x, 1);                                      \
    if (lane == 0)  _l  = (_ok && (LOK)) ? __ldg(&xc[_r*256 + (COL) - 1]) : 0.f; \
    if (lane == 31) _rv = (_ok && (ROK)) ? __ldg(&xc[_r*256 + (COL) + 2]) : 0.f; \
    (L) = _l; (C) = _c; (R) = _rv; } while(0)

// ---------------------------------------------------------------------------
// Pass 1: conv at K half-pixels, elu+1, in-thread rope (channel pair), kv+ksum.
__global__ void __launch_bounds__(128) k1_kv(
    const float* __restrict__ x,
    const float* __restrict__ qk_w,
    const float* __restrict__ qk_b)
{
    const int seg = blockIdx.x, ch = blockIdx.y, b = blockIdx.z;
    const int t = threadIdx.x;
    const int lane = t & 31;            // j: channel pair index
    const int w_id = t >> 5;
    const int s = w_id & 1, rg = w_id >> 1;
    const int j = lane;
    const int wk = 64 + s*128 + 2*j;    // image column of channel 2j (K half)
    const int h = j >> 3;
    const float* xb = x + (size_t)b * (64*NPIX);
    const float* xc = xb + (size_t)(ch >> 1) * NPIX;

    float w[9];
#pragma unroll
    for (int i = 0; i < 9; i++) w[i] = __ldg(&qk_w[ch*9 + i]);
    const float bias = __ldg(&qk_b[ch]);

    const int rs = seg*64 + rg*32;
    float l0,r0,l1,r1,l2,r2; float2 c0,c1,c2;
    const bool rok = (wk + 2 < 256);
    LDROW2(rs-1, l0,c0,r0, wk, 1, rok);
    LDROW2(rs,   l1,c1,r1, wk, 1, rok);
    LDROW2(rs+1, l2,c2,r2, wk, 1, rok);

    float acc0[16], acc1[16];
#pragma unroll
    for (int e = 0; e < 16; e++) { acc0[e] = 0.f; acc1[e] = 0.f; }
    float ksum0 = 0.f, ksum1 = 0.f;
    const float* vbase = xb + (size_t)ch*32768 + s*64 + h*16;

    float2 cs = __ldg(&g_cs[(((2*rs) + s) & 255)*32 + j]);
    const float4* vq = (const float4*)(vbase + (size_t)rs * 128);
    float4 va = __ldg(vq+0), vb2 = __ldg(vq+1), vc3 = __ldg(vq+2), vd = __ldg(vq+3);

    for (int hi = rs; hi < rs + 32; hi++) {
        int hn = (hi+1 < rs+32) ? hi+1 : rs;
        float2 cs_n = __ldg(&g_cs[(((2*hn) + s) & 255)*32 + j]);
        const float4* vn = (const float4*)(vbase + (size_t)hn * 128);
        float4 na = __ldg(vn+0), nb = __ldg(vn+1), nc = __ldg(vn+2), nd = __ldg(vn+3);

        float a0 = bias + w[0]*l0   + w[1]*c0.x + w[2]*c0.y
                        + w[3]*l1   + w[4]*c1.x + w[5]*c1.y
                        + w[6]*l2   + w[7]*c2.x + w[8]*c2.y;
        float a1 = bias + w[0]*c0.x + w[1]*c0.y + w[2]*r0
                        + w[3]*c1.x + w[4]*c1.y + w[5]*r1
                        + w[6]*c2.x + w[7]*c2.y + w[8]*r2;
        float k0v = (a0 > 0.f) ? (a0 + 1.f) : __expf(a0);
        float k1v = (a1 > 0.f) ? (a1 + 1.f) : __expf(a1);
        ksum0 += k0v; ksum1 += k1v;

        float kr0 = k0v*cs.x - k1v*cs.y;
        float kr1 = k0v*cs.y + k1v*cs.x;

        acc0[0] += kr0*va.x;  acc0[1] += kr0*va.y;  acc0[2] += kr0*va.z;  acc0[3] += kr0*va.w;
        acc0[4] += kr0*vb2.x; acc0[5] += kr0*vb2.y; acc0[6] += kr0*vb2.z; acc0[7] += kr0*vb2.w;
        acc0[8] += kr0*vc3.x; acc0[9] += kr0*vc3.y; acc0[10]+= kr0*vc3.z; acc0[11]+= kr0*vc3.w;
        acc0[12]+= kr0*vd.x;  acc0[13]+= kr0*vd.y;  acc0[14]+= kr0*vd.z;  acc0[15]+= kr0*vd.w;
        acc1[0] += kr1*va.x;  acc1[1] += kr1*va.y;  acc1[2] += kr1*va.z;  acc1[3] += kr1*va.w;
        acc1[4] += kr1*vb2.x; acc1[5] += kr1*vb2.y; acc1[6] += kr1*vb2.z; acc1[7] += kr1*vb2.w;
        acc1[8] += kr1*vc3.x; acc1[9] += kr1*vc3.y; acc1[10]+= kr1*vc3.z; acc1[11]+= kr1*vc3.w;
        acc1[12]+= kr1*vd.x;  acc1[13]+= kr1*vd.y;  acc1[14]+= kr1*vd.z;  acc1[15]+= kr1*vd.w;

        cs = cs_n; va = na; vb2 = nb; vc3 = nc; vd = nd;
        l0=l1; c0=c1; r0=r1;  l1=l2; c1=c2; r1=r2;
        LDROW2(hi+2, l2,c2,r2, wk, 1, rok);
    }

    __shared__ float red[32*128];       // [idx 0..31][w*32+j]
    __shared__ float red2[256];
#pragma unroll
    for (int e = 0; e < 16; e++) {
        red[e*128      + w_id*32 + j] = acc0[e];
        red[(16+e)*128 + w_id*32 + j] = acc1[e];
    }
    red2[w_id*64 + 2*j]     = ksum0;
    red2[w_id*64 + 2*j + 1] = ksum1;
    __syncthreads();
#pragma unroll
    for (int q = 0; q < 8; q++) {
        int s2 = t*8 + q;
        int idx = s2 >> 5, jv = s2 & 31;
        float v = red[idx*128 + jv] + red[idx*128 + 32 + jv]
                + red[idx*128 + 64 + jv] + red[idx*128 + 96 + jv];
        int d = 2*(jv & 7) + (idx >> 4);
        int e = idx & 15;
        int hh = jv >> 3;
        atomicAdd(&g_kv[b*1024 + hh*256 + d*16 + e], v);
    }
    if (t < 64) {
        float v = red2[t] + red2[64+t] + red2[128+t] + red2[192+t];
        atomicAdd(&g_ksum[b*64 + t], v);
    }
}

// ---------------------------------------------------------------------------
// Pass 2 (fused): conv at Q half-pixels, elu, z, rope, matvec vs float2 kv
// registers, PLUS lepe 3x3 via a sliding 3-row x 3-col float2 window (warp =
// all 64 channels of one image column, column advances by 2 per iteration).
// Staged coalesced transpose write of (attention + lepe).
__global__ void __launch_bounds__(128) k3a_attn(
    const float* __restrict__ x,
    const float* __restrict__ qk_w,
    const float* __restrict__ qk_b,
    const float* __restrict__ lepe_w,
    const float* __restrict__ lepe_b,
    float* __restrict__ out)
{
    const int seg = blockIdx.x, ch = blockIdx.y, b = blockIdx.z;
    const int t = threadIdx.x;
    const int lane = t & 31;            // j
    const int w_id = t >> 5;
    const int s = w_id & 1, rg = w_id >> 1;
    const int j = lane;
    const int wq = s*128 + 2*j;         // image column of channel 2j (Q half)
    const int h = j >> 3, e0 = 2*(j & 7);
    const float* xb = x + (size_t)b * (64*NPIX);
    const float* xc = xb + (size_t)(ch >> 1) * NPIX;

    float w[9];
#pragma unroll
    for (int i = 0; i < 9; i++) w[i] = __ldg(&qk_w[ch*9 + i]);
    const float bias = __ldg(&qk_b[ch]);
    const float ks0 = __ldg(&g_ksum[b*64 + 2*j]);
    const float ks1 = __ldg(&g_ksum[b*64 + 2*j + 1]);
    float2 kv2[16];
#pragma unroll
    for (int d = 0; d < 16; d++)
        kv2[d] = __ldg((const float2*)&g_kv[b*1024 + h*256 + d*16 + e0]);

    // lepe weights for channels 2j, 2j+1
    float lw0[9], lw1[9];
#pragma unroll
    for (int i = 0; i < 9; i++) {
        lw0[i] = __ldg(&lepe_w[(2*j)*9 + i]);
        lw1[i] = __ldg(&lepe_w[(2*j+1)*9 + i]);
    }
    const float lb0 = __ldg(&lepe_b[2*j]);
    const float lb1 = __ldg(&lepe_b[2*j + 1]);

    __shared__ __align__(16) float qs[4][2][64];
    __shared__ float res[2][64][66];

    const int rs = seg*64 + rg*32;
    const bool lok = (wq > 0);
    float l0,r0,l1,r1,l2,r2; float2 c0,c1,c2;
    LDROW2(rs-1, l0,c0,r0, wq, lok, 1);
    LDROW2(rs,   l1,c1,r1, wq, lok, 1);
    LDROW2(rs+1, l2,c2,r2, wq, lok, 1);

    float2 cs = __ldg(&g_cs[(((2*rs) + s) & 255)*32 + j]);

    // lepe geometry: warp covers columns col0 + 2*ii (parity s) of image row R
    const int R = 2*ch + (rs >> 7);
    const int col0 = (2*rs + s) & 255;
    const bool rv0 = (R >= 1), rv2 = (R <= 254);
    const float* lp0 = xb + ((size_t)(R-1)*256)*64 + 2*j;
    const float* lp1 = xb + ((size_t)(R  )*256)*64 + 2*j;
    const float* lp2 = xb + ((size_t)(R+1)*256)*64 + 2*j;

#define LPLD(rp, rv, cc) ((rv && (unsigned)(cc) < 256u) ? \
        __ldg((const float2*)((rp) + (size_t)(cc)*64)) : make_float2(0.f,0.f))

    float2 M0 = LPLD(lp0, rv0, col0-1), M1 = LPLD(lp1, true, col0-1), M2 = LPLD(lp2, rv2, col0-1);
    float2 C0 = LPLD(lp0, rv0, col0),   C1 = LPLD(lp1, true, col0),   C2 = LPLD(lp2, rv2, col0);
    float2 P0 = LPLD(lp0, rv0, col0+1), P1 = LPLD(lp1, true, col0+1), P2 = LPLD(lp2, rv2, col0+1);

    for (int ii = 0; ii < 32; ii++) {
        const int hi = rs + ii;
        const int col = col0 + 2*ii;
        int hn = (ii+1 < 32) ? hi+1 : hi;
        float2 cs_n = __ldg(&g_cs[(((2*hn) + s) & 255)*32 + j]);
        // prefetch next lepe columns (col+2, col+3)
        float2 N0a = LPLD(lp0, rv0, col+2), N1a = LPLD(lp1, true, col+2), N2a = LPLD(lp2, rv2, col+2);
        float2 N0b = LPLD(lp0, rv0, col+3), N1b = LPLD(lp1, true, col+3), N2b = LPLD(lp2, rv2, col+3);

        // conv + elu
        float a0 = bias + w[0]*l0   + w[1]*c0.x + w[2]*c0.y
                        + w[3]*l1   + w[4]*c1.x + w[5]*c1.y
                        + w[6]*l2   + w[7]*c2.x + w[8]*c2.y;
        float a1 = bias + w[0]*c0.x + w[1]*c0.y + w[2]*r0
                        + w[3]*c1.x + w[4]*c1.y + w[5]*r1
                        + w[6]*c2.x + w[7]*c2.y + w[8]*r2;
        float q0 = (a0 > 0.f) ? (a0 + 1.f) : __expf(a0);
        float q1 = (a1 > 0.f) ? (a1 + 1.f) : __expf(a1);

        // z: 8-lane segment reduce
        float zp = q0*ks0 + q1*ks1;
        zp += __shfl_xor_sync(FULL, zp, 1);
        zp += __shfl_xor_sync(FULL, zp, 2);
        zp += __shfl_xor_sync(FULL, zp, 4);
        float z = 1.f / (zp * INV_N + 1e-6f);

        // in-thread rope
        float qr0 = q0*cs.x - q1*cs.y;
        float qr1 = q0*cs.y + q1*cs.x;

        const int buf = ii & 1;
        *(float2*)&qs[w_id][buf][2*j] = make_float2(qr0, qr1);
        __syncwarp();
        const float4* qp = (const float4*)&qs[w_id][buf][h*16];
        float4 qa = qp[0], qb2 = qp[1], qc3 = qp[2], qd = qp[3];

        float o0 = qa.x*kv2[0].x  + qa.y*kv2[1].x  + qa.z*kv2[2].x  + qa.w*kv2[3].x
                 + qb2.x*kv2[4].x + qb2.y*kv2[5].x + qb2.z*kv2[6].x + qb2.w*kv2[7].x
                 + qc3.x*kv2[8].x + qc3.y*kv2[9].x + qc3.z*kv2[10].x+ qc3.w*kv2[11].x
                 + qd.x*kv2[12].x + qd.y*kv2[13].x + qd.z*kv2[14].x + qd.w*kv2[15].x;
        float o1 = qa.x*kv2[0].y  + qa.y*kv2[1].y  + qa.z*kv2[2].y  + qa.w*kv2[3].y
                 + qb2.x*kv2[4].y + qb2.y*kv2[5].y + qb2.z*kv2[6].y + qb2.w*kv2[7].y
                 + qc3.x*kv2[8].y + qc3.y*kv2[9].y + qc3.z*kv2[10].y+ qc3.w*kv2[11].y
                 + qd.x*kv2[12].y + qd.y*kv2[13].y + qd.z*kv2[14].y + qd.w*kv2[15].y;
        float zz = z * INV_N;
        o0 *= zz; o1 *= zz;

        // lepe taps at (R, col), channels 2j (x) and 2j+1 (y)
        o0 += lb0 + lw0[0]*M0.x + lw0[1]*C0.x + lw0[2]*P0.x
                  + lw0[3]*M1.x + lw0[4]*C1.x + lw0[5]*P1.x
                  + lw0[6]*M2.x + lw0[7]*C2.x + lw0[8]*P2.x;
        o1 += lb1 + lw1[0]*M0.y + lw1[1]*C0.y + lw1[2]*P0.y
                  + lw1[3]*M1.y + lw1[4]*C1.y + lw1[5]*P1.y
                  + lw1[6]*M2.y + lw1[7]*C2.y + lw1[8]*P2.y;

        const int pos = 2*(rg*32 + ii) + s;     // 0..127
        const int chunk = pos >> 6, p = pos & 63;
        res[chunk][2*j][p]   = o0;
        res[chunk][2*j+1][p] = o1;

        // slide lepe window by 2 columns
        M0 = P0; M1 = P1; M2 = P2;
        C0 = N0a; C1 = N1a; C2 = N2a;
        P0 = N0b; P1 = N1b; P2 = N2b;

        cs = cs_n;
        l0=l1; c0=c1; r0=r1;  l1=l2; c1=c2; r1=r2;
        LDROW2(hi+2, l2,c2,r2, wq, lok, 1);
    }
#undef LPLD

    __syncthreads();
    float* ob = out + (size_t)b * (64*NPIX);
    const int nbase = ch*512 + seg*128;
    for (int ci = w_id; ci < 64; ci += 4) {
        float2 v0 = *(const float2*)&res[0][ci][2*lane];
        float2 v1 = *(const float2*)&res[1][ci][2*lane];
        *(float2*)&ob[(size_t)ci*NPIX + nbase + 2*lane]      = v0;
        *(float2*)&ob[(size_t)ci*NPIX + nbase + 64 + 2*lane] = v1;
    }
}

// ---------------------------------------------------------------------------
extern "C" void kernel_launch(void* const* d_in, const int* in_sizes, int n_in,
                              void* d_out, int out_size) {
    (void)in_sizes; (void)n_in; (void)out_size;
    const float* x      = (const float*)d_in[0];
    const float* qk_w   = (const float*)d_in[1];
    const float* qk_b   = (const float*)d_in[2];
    const float* lepe_w = (const float*)d_in[3];
    const float* lepe_b = (const float*)d_in[4];
    float* out = (float*)d_out;

    k0_init<<<32, 256>>>();
    k1_kv<<<dim3(4, 128, BATCH), 128>>>(x, qk_w, qk_b);
    k3a_attn<<<dim3(4, 128, BATCH), 128>>>(x, qk_w, qk_b, lepe_w, lepe_b, out);
}